// round 13
// baseline (speedup 1.0000x reference)
#include <cuda_runtime.h>
#include <cstdint>

// ---------------------------------------------------------------------------
// ZigzagAttention  B=2 S=4096 D=1024 H=16 depth=64 — tf32 mma, single-pass attn
// d_out (fp32): [0,8388608) out[2,4096,1024]; then w_odd, w_even [2,16,2048,2048]
// ---------------------------------------------------------------------------

#define DINL __device__ __forceinline__

static __device__ float g_qh[8388608];    // [z][t][64]   z=(b*16+h)*2+half
static __device__ float g_kh[8388608];    // [z][t][64]
static __device__ float g_vh[8388608];    // [z][d][t]  (TRANSPOSED)
static __device__ float g_attn[8388608];  // [b][4096][1024]
static __device__ float g_wfallback[268435456];

DINL float tf32r(float x){ uint32_t u; asm("cvt.rna.tf32.f32 %0, %1;" : "=r"(u) : "f"(x)); return __uint_as_float(u); }
DINL uint32_t fu(float x){ return __float_as_uint(x); }
DINL float ex2(float x){ float r; asm("ex2.approx.f32 %0, %1;" : "=f"(r) : "f"(x)); return r; }

#define EXPSC 0.18033688011111793f   // 0.125 * log2(e)

DINL void mma8(float d[4], float a0, float a1, float a2, float a3, float b0, float b1){
  asm volatile("mma.sync.aligned.m16n8k8.row.col.f32.tf32.tf32.f32 "
    "{%0,%1,%2,%3}, {%4,%5,%6,%7}, {%8,%9}, {%0,%1,%2,%3};"
    : "+f"(d[0]), "+f"(d[1]), "+f"(d[2]), "+f"(d[3])
    : "r"(fu(a0)), "r"(fu(a1)), "r"(fu(a2)), "r"(fu(a3)), "r"(fu(b0)), "r"(fu(b1)));
}

// ---------------------------------------------------------------------------
// Swizzled SMEM tile, R rows x 32 k. Element (r,k):
//   addr = r*32 + (((k>>4)&1)^(r&1))*16 + (((k&3)^((r>>1)&3))<<2) + ((k>>2)&3)
// Fragment float4 at (r,gg,c) = k{16gg+c,+4,+8,+12}.
// ---------------------------------------------------------------------------
template<int NIT>
DINL void ldgN(float4 v[NIT], const float* src, int lds, int tid){
  const int lane = tid & 31;
  const int j = lane >> 2;
  int r = ((tid >> 5) << 2) + (lane & 3);
  #pragma unroll
  for (int i = 0; i < NIT; i++, r += 32)
    v[i] = *(const float4*)(src + (size_t)r * lds + (j << 2));
}
DINL void sts1(float* buf, float4 v, int r, int gg, int q){
  const int s = (r >> 1) & 3;
  float* p = buf + r*32 + ((gg ^ (r & 1)) << 4) + q;
  p[((0 ^ s) << 2)] = tf32r(v.x);
  p[((1 ^ s) << 2)] = tf32r(v.y);
  p[((2 ^ s) << 2)] = tf32r(v.z);
  p[((3 ^ s) << 2)] = tf32r(v.w);
}
template<int NIT>
DINL void stsN(float* buf, const float4 v[NIT], int tid){
  const int lane = tid & 31;
  const int j = lane >> 2;
  const int gg = j >> 2, q = j & 3;
  int r = ((tid >> 5) << 2) + (lane & 3);
  #pragma unroll
  for (int i = 0; i < NIT; i++, r += 32) sts1(buf, v[i], r, gg, q);
}

// 256-thread direct loader: R rows, lds arbitrary
template<int R>
DINL void load_tile256(float* buf, const float* src, int lds, int tid){
  const int lane = tid & 31;
  const int j = lane >> 2;
  const int gg = j >> 2, q = j & 3;
  int r = ((tid >> 5) << 2) + (lane & 3);
  #pragma unroll
  for (int i = 0; i < R/32; i++, r += 32){
    float4 v = *(const float4*)(src + (size_t)r * lds + (j << 2));
    sts1(buf, v, r, gg, q);
  }
}

template<int MF, int NF>
DINL void mma_core(const float* As, const float* Bs, int lane, int wm, int wn, float acc[MF][NF][4]){
  const int c = lane & 3, lr = lane >> 2;
  #pragma unroll
  for (int gg = 0; gg < 2; gg++){
    float4 alo[MF], ahi[MF], bf[NF];
    #pragma unroll
    for (int mf = 0; mf < MF; mf++){
      int m0 = wm + mf*16 + lr;
      const float* pa = As + m0*32 + ((gg ^ (m0 & 1)) << 4) + ((c ^ ((m0 >> 1) & 3)) << 2);
      alo[mf] = *(const float4*)pa;
      ahi[mf] = *(const float4*)(pa + 256);
    }
    #pragma unroll
    for (int nf = 0; nf < NF; nf++){
      int n = wn + nf*8 + lr;
      bf[nf] = *(const float4*)(Bs + n*32 + ((gg ^ (n & 1)) << 4) + ((c ^ ((n >> 1) & 3)) << 2));
    }
    #pragma unroll
    for (int mf = 0; mf < MF; mf++)
      #pragma unroll
      for (int nf = 0; nf < NF; nf++){
        mma8(acc[mf][nf], alo[mf].x, ahi[mf].x, alo[mf].y, ahi[mf].y, bf[nf].x, bf[nf].y);
        mma8(acc[mf][nf], alo[mf].z, ahi[mf].z, alo[mf].w, ahi[mf].w, bf[nf].z, bf[nf].w);
      }
  }
}

// ---------------------------------------------------------------------------
// Dense GEMM body: 256 thr, 8 warps, CTA tile 256m x 128n, warp tile 64x64,
// BK=32 double-buffered (96KB smem). mode 0: q/k scatter, 1: fc, 2: v^T
// ---------------------------------------------------------------------------
DINL void gemm_db(const float* X, const float* W, const float* bias,
                  float* outp, int mode, int bm, int bn, float* sm, int tid){
  const int lane = tid & 31, w = tid >> 5;
  const int wm = (w >> 1) * 64, wn = (w & 1) * 64;
  float acc[4][8][4] = {};
  float4 va[8], vb[4];
  ldgN<8>(va, X + (size_t)bm*1024, 1024, tid);
  ldgN<4>(vb, W + (size_t)bn*1024, 1024, tid);
  stsN<8>(sm,        va, tid);
  stsN<4>(sm + 8192, vb, tid);
  __syncthreads();
  #pragma unroll 1
  for (int k0 = 0; k0 < 1024; k0 += 32){
    const int cur = (k0 >> 5) & 1;
    float* sc = sm + cur*12288;
    const bool more = (k0 + 32 < 1024);
    if (more){
      ldgN<8>(va, X + (size_t)bm*1024 + k0 + 32, 1024, tid);
      ldgN<4>(vb, W + (size_t)bn*1024 + k0 + 32, 1024, tid);
    }
    mma_core<4,8>(sc, sc + 8192, lane, wm, wn, acc);
    if (more){
      float* sn = sm + (cur^1)*12288;
      stsN<8>(sn,        va, tid);
      stsN<4>(sn + 8192, vb, tid);
      __syncthreads();
    }
  }
  const int c2 = (lane & 3) * 2, lr = lane >> 2;
  #pragma unroll
  for (int mf = 0; mf < 4; mf++)
    #pragma unroll
    for (int rr = 0; rr < 2; rr++){
      int m = bm + wm + mf*16 + lr + rr*8;
      #pragma unroll
      for (int nf = 0; nf < 8; nf++){
        int n = bn + wn + nf*8 + c2;
        float2 bv = *(const float2*)(bias + n);
        float2 o; o.x = acc[mf][nf][rr*2+0] + bv.x; o.y = acc[mf][nf][rr*2+1] + bv.y;
        if (mode == 0){
          int b = m >> 12, s = m & 4095;
          size_t rbase = (size_t)b*4194304 + (size_t)(s & 1)*131072 + (size_t)(s >> 1)*64;
          *(float2*)(outp + rbase + (size_t)(n >> 6)*262144 + (n & 63)) = o;
        } else if (mode == 1){
          *(float2*)(outp + (size_t)m*1024 + n) = o;
        } else {
          int b = m >> 12, s = m & 4095;
          int h = n >> 6, d = n & 63;
          size_t zb = ((size_t)(b*16 + h)*2 + (s & 1)) * 131072 + (size_t)(s >> 1);
          outp[zb + (size_t)d*2048]       = o.x;
          outp[zb + (size_t)(d+1)*2048]   = o.y;
        }
      }
    }
}

__global__ __launch_bounds__(256) void proj3_tc(
    const float* __restrict__ q, const float* __restrict__ k, const float* __restrict__ v,
    const float* __restrict__ wq_w, const float* __restrict__ wq_b,
    const float* __restrict__ wk_w, const float* __restrict__ wk_b,
    const float* __restrict__ wv_w, const float* __restrict__ wv_b){
  extern __shared__ float sm[];
  const int which = blockIdx.z;
  const float* X = (which == 0) ? q : (which == 1) ? k : v;
  const float* W = (which == 0) ? wq_w : (which == 1) ? wk_w : wv_w;
  const float* B = (which == 0) ? wq_b : (which == 1) ? wk_b : wv_b;
  float* outp = (which == 0) ? g_qh : (which == 1) ? g_kh : g_vh;
  gemm_db(X, W, B, outp, (which == 2) ? 2 : 0, blockIdx.y*256, blockIdx.x*128, sm, threadIdx.x);
}

__global__ __launch_bounds__(256) void fc_tc(const float* __restrict__ W,
    const float* __restrict__ bias, float* __restrict__ out){
  extern __shared__ float sm[];
  gemm_db(g_attn, W, bias, out, 1, blockIdx.y*256, blockIdx.x*128, sm, threadIdx.x);
}

// ---------------------------------------------------------------------------
// Single-pass fused attention + in-kernel w normalization.
// 256 threads, 8 warps x 32 m-rows (MF=2), m-tile 256 rows, Q IN REGISTERS.
// Q is staged coalesced through smem once, fragments read to regs, then the
// same smem becomes the K/V ping-pong (64KB total). Hot loop has zero
// A-operand LDS; K B-frags + loader STS amortize over 2x rows; V B-frags
// feed both mf halves. p = ex2(s*0.125*log2e); unnormalized p -> w region;
// tail normalizes the block's own 256-row stripe.
// ---------------------------------------------------------------------------
__global__ __launch_bounds__(256) void attn_tc(float* w_region, int use_out){
  extern __shared__ float smem[];          // 16384 floats = 64KB (KV ping-pong)
  float* w_base = use_out ? w_region : g_wfallback;

  const int z = blockIdx.y;
  const int half = z & 1, bh = z >> 1, b = bh >> 4, h = bh & 15;
  const float* Q  = g_qh + (size_t)z * 131072;
  const float* Kp = g_kh + (size_t)z * 131072;
  const float* Vt = g_vh + (size_t)z * 131072;   // [d][t]
  float* Wout = w_base + (size_t)half * 134217728 + (size_t)bh * 4194304;

  const int tid = threadIdx.x, lane = tid & 31, w = tid >> 5;
  const int bm = blockIdx.x * 256;
  const int wm = w * 32;
  const int c = lane & 3, c2 = c * 2, lr = lane >> 2;
  const unsigned src0 = (lane & 28) | (c >> 1);
  const unsigned src1 = src0 | 2;
  const bool codd = (c & 1);

  // ---- stage Q through smem (coalesced), pull fragments into registers ----
  float4 qf[2][2][2][2];   // [mf][ch][gg][lo/hi]
  {
    load_tile256<256>(smem,        Q + (size_t)bm*64 + 0,  64, tid);
    load_tile256<256>(smem + 8192, Q + (size_t)bm*64 + 32, 64, tid);
    __syncthreads();
    #pragma unroll
    for (int mf = 0; mf < 2; mf++)
      #pragma unroll
      for (int ch = 0; ch < 2; ch++)
        #pragma unroll
        for (int gg = 0; gg < 2; gg++)
          #pragma unroll
          for (int hh = 0; hh < 2; hh++){
            const int r = wm + mf*16 + lr + hh*8;
            qf[mf][ch][gg][hh] = *(const float4*)(smem + ch*8192 + r*32 +
                ((gg ^ (r & 1)) << 4) + ((c ^ ((r >> 1) & 3)) << 2));
          }
    __syncthreads();
  }

  // ---- preload K/V tile 0 into buffer 0 ----
  {
    float* Kb = smem;
    float* Vb = smem + 4096;
    load_tile256<64>(Kb,        Kp + 0,  64, tid);
    load_tile256<64>(Kb + 2048, Kp + 32, 64, tid);
    load_tile256<64>(Vb,        Vt + 0,  2048, tid);
    load_tile256<64>(Vb + 2048, Vt + 32, 2048, tid);
  }

  float lrow[4] = {0.f, 0.f, 0.f, 0.f};
  float oacc[2][8][4] = {};

  #pragma unroll 1
  for (int nt = 0; nt < 32; nt++){
    __syncthreads();
    float* Kb = smem + (nt & 1)*8192;
    float* Vb = Kb + 4096;
    if (nt < 31){
      float* Kn = smem + ((nt+1) & 1)*8192;
      float* Vn = Kn + 4096;
      load_tile256<64>(Kn,        Kp + (size_t)(nt+1)*4096 + 0,  64, tid);
      load_tile256<64>(Kn + 2048, Kp + (size_t)(nt+1)*4096 + 32, 64, tid);
      load_tile256<64>(Vn,        Vt + (nt+1)*64 + 0,  2048, tid);
      load_tile256<64>(Vn + 2048, Vt + (nt+1)*64 + 32, 2048, tid);
    }

    // ---- QK^T: A from registers, B from smem (one load serves both mf) ----
    float sacc[2][8][4] = {};
    #pragma unroll
    for (int ch = 0; ch < 2; ch++){
      const float* Kc = Kb + ch*2048;
      #pragma unroll
      for (int gg = 0; gg < 2; gg++){
        #pragma unroll
        for (int nf = 0; nf < 8; nf++){
          const int n = nf*8 + lr;
          float4 bf = *(const float4*)(Kc + n*32 + ((gg ^ (n & 1)) << 4) + ((c ^ ((n >> 1) & 3)) << 2));
          #pragma unroll
          for (int mf = 0; mf < 2; mf++){
            mma8(sacc[mf][nf], qf[mf][ch][gg][0].x, qf[mf][ch][gg][1].x,
                               qf[mf][ch][gg][0].y, qf[mf][ch][gg][1].y, bf.x, bf.y);
            mma8(sacc[mf][nf], qf[mf][ch][gg][0].z, qf[mf][ch][gg][1].z,
                               qf[mf][ch][gg][0].w, qf[mf][ch][gg][1].w, bf.z, bf.w);
          }
        }
      }
    }

    // ---- p = ex2(s*c), store unnormalized w, round p in place for PV ----
    #pragma unroll
    for (int mf = 0; mf < 2; mf++)
      #pragma unroll
      for (int rr = 0; rr < 2; rr++){
        const int r = wm + mf*16 + lr + rr*8;
        size_t gbase = (size_t)(bm + r) * 2048 + nt*64 + c2;
        float lsum = 0.f;
        #pragma unroll
        for (int nf = 0; nf < 8; nf++){
          float v0 = ex2(sacc[mf][nf][rr*2]   * EXPSC);
          float v1 = ex2(sacc[mf][nf][rr*2+1] * EXPSC);
          lsum += v0 + v1;
          *(float2*)(Wout + gbase + nf*8) = make_float2(v0, v1);
          sacc[mf][nf][rr*2]   = tf32r(v0);
          sacc[mf][nf][rr*2+1] = tf32r(v1);
        }
        lrow[mf*2 + rr] += lsum;
      }

    // ---- PV: O += p @ V; A-frags via shuffles; one V load serves both mf ----
    #pragma unroll
    for (int ch = 0; ch < 2; ch++){
      const float* Vc = Vb + ch*2048;
      #pragma unroll
      for (int gg = 0; gg < 2; gg++){
        float A2[2][2][4];   // [mf][hh][4]
        #pragma unroll
        for (int mf = 0; mf < 2; mf++)
          #pragma unroll
          for (int hh = 0; hh < 2; hh++){
            const int g = ch*4 + gg*2 + hh;
            float s0 = __shfl_sync(0xffffffffu, sacc[mf][g][0], src0);
            float s1 = __shfl_sync(0xffffffffu, sacc[mf][g][1], src0);
            float s2 = __shfl_sync(0xffffffffu, sacc[mf][g][2], src0);
            float s3 = __shfl_sync(0xffffffffu, sacc[mf][g][3], src0);
            A2[mf][hh][0] = codd ? s1 : s0;
            A2[mf][hh][1] = codd ? s3 : s2;
            float t0 = __shfl_sync(0xffffffffu, sacc[mf][g][0], src1);
            float t1 = __shfl_sync(0xffffffffu, sacc[mf][g][1], src1);
            float t2 = __shfl_sync(0xffffffffu, sacc[mf][g][2], src1);
            float t3 = __shfl_sync(0xffffffffu, sacc[mf][g][3], src1);
            A2[mf][hh][2] = codd ? t1 : t0;
            A2[mf][hh][3] = codd ? t3 : t2;
          }
        #pragma unroll
        for (int nf = 0; nf < 8; nf++){
          const int n = nf*8 + lr;
          float4 bf = *(const float4*)(Vc + n*32 + ((gg ^ (n & 1)) << 4) + ((c ^ ((n >> 1) & 3)) << 2));
          #pragma unroll
          for (int mf = 0; mf < 2; mf++){
            mma8(oacc[mf][nf], A2[mf][0][0], A2[mf][0][1], A2[mf][0][2], A2[mf][0][3], bf.x, bf.y);
            mma8(oacc[mf][nf], A2[mf][1][0], A2[mf][1][1], A2[mf][1][2], A2[mf][1][3], bf.z, bf.w);
          }
        }
      }
    }
  }

  // quad-reduce row sums, invert
  float invl[4];
  #pragma unroll
  for (int si = 0; si < 4; si++){
    float s = lrow[si];
    s += __shfl_xor_sync(0xffffffffu, s, 1);
    s += __shfl_xor_sync(0xffffffffu, s, 2);
    invl[si] = 1.0f / s;
  }

  // O epilogue (scaled): g_attn[b][half*2048+m][h*64+d]
  #pragma unroll
  for (int mf = 0; mf < 2; mf++)
    #pragma unroll
    for (int rr = 0; rr < 2; rr++){
      int m = bm + wm + mf*16 + lr + rr*8;
      const float s = invl[mf*2 + rr];
      size_t obase = ((size_t)b*4096 + (size_t)half*2048 + m) * 1024 + h*64;
      #pragma unroll
      for (int nf = 0; nf < 8; nf++){
        int d = nf*8 + c2;
        float2 o;
        o.x = oacc[mf][nf][rr*2+0] * s;
        o.y = oacc[mf][nf][rr*2+1] * s;
        *(float2*)(g_attn + obase + d) = o;
      }
    }

  // ---- tail: normalize this block's own 256 w rows ----
  __syncthreads();                 // all in-loop w STGs done; smem free
  if (c == 0){
    #pragma unroll
    for (int mf = 0; mf < 2; mf++){
      smem[wm + mf*16 + lr]     = invl[mf*2 + 0];
      smem[wm + mf*16 + lr + 8] = invl[mf*2 + 1];
    }
  }
  __syncthreads();
  float4* wp = (float4*)(Wout + (size_t)bm * 2048);
  #pragma unroll 4
  for (int i = tid; i < 256*512; i += 256){
    const int row = i >> 9;
    const float s = smem[row];
    float4 v = wp[i];
    v.x *= s; v.y *= s; v.z *= s; v.w *= s;
    wp[i] = v;
  }
}

// ---------------------------------------------------------------------------
extern "C" void kernel_launch(void* const* d_in, const int* in_sizes, int n_in,
                              void* d_out, int out_size)
{
  const float* q    = (const float*)d_in[0];
  const float* k    = (const float*)d_in[1];
  const float* v    = (const float*)d_in[2];
  const float* wq_w = (const float*)d_in[3];
  const float* wq_b = (const float*)d_in[4];
  const float* wk_w = (const float*)d_in[5];
  const float* wk_b = (const float*)d_in[6];
  const float* wv_w = (const float*)d_in[7];
  const float* wv_b = (const float*)d_in[8];
  const float* fc_w = (const float*)d_in[9];
  const float* fc_b = (const float*)d_in[10];
  float* out = (float*)d_out;

  const int w_in_out = (out_size >= 276824064) ? 1 : 0;
  float* w_region = out + 8388608;

  cudaFuncSetAttribute(attn_tc,  cudaFuncAttributeMaxDynamicSharedMemorySize, 65536);
  cudaFuncSetAttribute(proj3_tc, cudaFuncAttributeMaxDynamicSharedMemorySize, 98304);
  cudaFuncSetAttribute(fc_tc,    cudaFuncAttributeMaxDynamicSharedMemorySize, 98304);

  proj3_tc<<<dim3(8, 32, 3), 256, 98304>>>(q, k, v, wq_w, wq_b, wk_w, wk_b, wv_w, wv_b);
  attn_tc<<<dim3(8, 64), 256, 65536>>>(w_region, w_in_out);
  fc_tc<<<dim3(8, 32), 256, 98304>>>(fc_w, fc_b, out);
}

// round 14
// speedup vs baseline: 1.1477x; 1.1477x over previous
#include <cuda_runtime.h>
#include <cstdint>

// ---------------------------------------------------------------------------
// ZigzagAttention  B=2 S=4096 D=1024 H=16 depth=64 — tf32 mma, single-pass attn
// d_out (fp32): [0,8388608) out[2,4096,1024]; then w_odd, w_even [2,16,2048,2048]
// ---------------------------------------------------------------------------

#define DINL __device__ __forceinline__

static __device__ float g_qh[8388608];    // [z][t][64]   z=(b*16+h)*2+half
static __device__ float g_kh[8388608];    // [z][t][64]
static __device__ float g_vh[8388608];    // [z][d][t]  (TRANSPOSED)
static __device__ float g_attn[8388608];  // [b][4096][1024]
static __device__ float g_wfallback[268435456];

DINL float tf32r(float x){ uint32_t u; asm("cvt.rna.tf32.f32 %0, %1;" : "=r"(u) : "f"(x)); return __uint_as_float(u); }
DINL uint32_t fu(float x){ return __float_as_uint(x); }

DINL void mma8(float d[4], float a0, float a1, float a2, float a3, float b0, float b1){
  asm volatile("mma.sync.aligned.m16n8k8.row.col.f32.tf32.tf32.f32 "
    "{%0,%1,%2,%3}, {%4,%5,%6,%7}, {%8,%9}, {%0,%1,%2,%3};"
    : "+f"(d[0]), "+f"(d[1]), "+f"(d[2]), "+f"(d[3])
    : "r"(fu(a0)), "r"(fu(a1)), "r"(fu(a2)), "r"(fu(a3)), "r"(fu(b0)), "r"(fu(b1)));
}

// ---------------------------------------------------------------------------
// Swizzled SMEM tile, R rows x 32 k. Element (r,k):
//   addr = r*32 + (((k>>4)&1)^(r&1))*16 + (((k&3)^((r>>1)&3))<<2) + ((k>>2)&3)
// Fragment float4 at (r,gg,c) = k{16gg+c,+4,+8,+12}.
// ---------------------------------------------------------------------------
template<int NIT>
DINL void ldgN(float4 v[NIT], const float* src, int lds, int tid){
  const int lane = tid & 31;
  const int j = lane >> 2;
  int r = ((tid >> 5) << 2) + (lane & 3);
  #pragma unroll
  for (int i = 0; i < NIT; i++, r += 32)
    v[i] = *(const float4*)(src + (size_t)r * lds + (j << 2));
}
DINL void sts1(float* buf, float4 v, int r, int gg, int q){
  const int s = (r >> 1) & 3;
  float* p = buf + r*32 + ((gg ^ (r & 1)) << 4) + q;
  p[((0 ^ s) << 2)] = tf32r(v.x);
  p[((1 ^ s) << 2)] = tf32r(v.y);
  p[((2 ^ s) << 2)] = tf32r(v.z);
  p[((3 ^ s) << 2)] = tf32r(v.w);
}
template<int NIT>
DINL void stsN(float* buf, const float4 v[NIT], int tid){
  const int lane = tid & 31;
  const int j = lane >> 2;
  const int gg = j >> 2, q = j & 3;
  int r = ((tid >> 5) << 2) + (lane & 3);
  #pragma unroll
  for (int i = 0; i < NIT; i++, r += 32) sts1(buf, v[i], r, gg, q);
}

// 256-thread direct loader: R rows, lds arbitrary
template<int R>
DINL void load_tile256(float* buf, const float* src, int lds, int tid){
  const int lane = tid & 31;
  const int j = lane >> 2;
  const int gg = j >> 2, q = j & 3;
  int r = ((tid >> 5) << 2) + (lane & 3);
  #pragma unroll
  for (int i = 0; i < R/32; i++, r += 32){
    float4 v = *(const float4*)(src + (size_t)r * lds + (j << 2));
    sts1(buf, v, r, gg, q);
  }
}

template<int MF, int NF>
DINL void mma_core(const float* As, const float* Bs, int lane, int wm, int wn, float acc[MF][NF][4]){
  const int c = lane & 3, lr = lane >> 2;
  #pragma unroll
  for (int gg = 0; gg < 2; gg++){
    float4 alo[MF], ahi[MF], bf[NF];
    #pragma unroll
    for (int mf = 0; mf < MF; mf++){
      int m0 = wm + mf*16 + lr;
      const float* pa = As + m0*32 + ((gg ^ (m0 & 1)) << 4) + ((c ^ ((m0 >> 1) & 3)) << 2);
      alo[mf] = *(const float4*)pa;
      ahi[mf] = *(const float4*)(pa + 256);
    }
    #pragma unroll
    for (int nf = 0; nf < NF; nf++){
      int n = wn + nf*8 + lr;
      bf[nf] = *(const float4*)(Bs + n*32 + ((gg ^ (n & 1)) << 4) + ((c ^ ((n >> 1) & 3)) << 2));
    }
    #pragma unroll
    for (int mf = 0; mf < MF; mf++)
      #pragma unroll
      for (int nf = 0; nf < NF; nf++){
        mma8(acc[mf][nf], alo[mf].x, ahi[mf].x, alo[mf].y, ahi[mf].y, bf[nf].x, bf[nf].y);
        mma8(acc[mf][nf], alo[mf].z, ahi[mf].z, alo[mf].w, ahi[mf].w, bf[nf].z, bf[nf].w);
      }
  }
}

// ---------------------------------------------------------------------------
// Dense GEMM body: 256 thr, 8 warps, CTA tile 256m x 128n, warp tile 64x64,
// BK=32 double-buffered (96KB smem). mode 0: q/k scatter, 1: fc, 2: v^T
// ---------------------------------------------------------------------------
DINL void gemm_db(const float* X, const float* W, const float* bias,
                  float* outp, int mode, int bm, int bn, float* sm, int tid){
  const int lane = tid & 31, w = tid >> 5;
  const int wm = (w >> 1) * 64, wn = (w & 1) * 64;
  float acc[4][8][4] = {};
  float4 va[8], vb[4];
  ldgN<8>(va, X + (size_t)bm*1024, 1024, tid);
  ldgN<4>(vb, W + (size_t)bn*1024, 1024, tid);
  stsN<8>(sm,        va, tid);
  stsN<4>(sm + 8192, vb, tid);
  __syncthreads();
  #pragma unroll 1
  for (int k0 = 0; k0 < 1024; k0 += 32){
    const int cur = (k0 >> 5) & 1;
    float* sc = sm + cur*12288;
    const bool more = (k0 + 32 < 1024);
    if (more){
      ldgN<8>(va, X + (size_t)bm*1024 + k0 + 32, 1024, tid);
      ldgN<4>(vb, W + (size_t)bn*1024 + k0 + 32, 1024, tid);
    }
    mma_core<4,8>(sc, sc + 8192, lane, wm, wn, acc);
    if (more){
      float* sn = sm + (cur^1)*12288;
      stsN<8>(sn,        va, tid);
      stsN<4>(sn + 8192, vb, tid);
      __syncthreads();
    }
  }
  const int c2 = (lane & 3) * 2, lr = lane >> 2;
  #pragma unroll
  for (int mf = 0; mf < 4; mf++)
    #pragma unroll
    for (int rr = 0; rr < 2; rr++){
      int m = bm + wm + mf*16 + lr + rr*8;
      #pragma unroll
      for (int nf = 0; nf < 8; nf++){
        int n = bn + wn + nf*8 + c2;
        float2 bv = *(const float2*)(bias + n);
        float2 o; o.x = acc[mf][nf][rr*2+0] + bv.x; o.y = acc[mf][nf][rr*2+1] + bv.y;
        if (mode == 0){
          int b = m >> 12, s = m & 4095;
          size_t rbase = (size_t)b*4194304 + (size_t)(s & 1)*131072 + (size_t)(s >> 1)*64;
          *(float2*)(outp + rbase + (size_t)(n >> 6)*262144 + (n & 63)) = o;
        } else if (mode == 1){
          *(float2*)(outp + (size_t)m*1024 + n) = o;
        } else {
          int b = m >> 12, s = m & 4095;
          int h = n >> 6, d = n & 63;
          size_t zb = ((size_t)(b*16 + h)*2 + (s & 1)) * 131072 + (size_t)(s >> 1);
          outp[zb + (size_t)d*2048]       = o.x;
          outp[zb + (size_t)(d+1)*2048]   = o.y;
        }
      }
    }
}

__global__ __launch_bounds__(256) void proj3_tc(
    const float* __restrict__ q, const float* __restrict__ k, const float* __restrict__ v,
    const float* __restrict__ wq_w, const float* __restrict__ wq_b,
    const float* __restrict__ wk_w, const float* __restrict__ wk_b,
    const float* __restrict__ wv_w, const float* __restrict__ wv_b){
  extern __shared__ float sm[];
  const int which = blockIdx.z;
  const float* X = (which == 0) ? q : (which == 1) ? k : v;
  const float* W = (which == 0) ? wq_w : (which == 1) ? wk_w : wv_w;
  const float* B = (which == 0) ? wq_b : (which == 1) ? wk_b : wv_b;
  float* outp = (which == 0) ? g_qh : (which == 1) ? g_kh : g_vh;
  gemm_db(X, W, B, outp, (which == 2) ? 2 : 0, blockIdx.y*256, blockIdx.x*128, sm, threadIdx.x);
}

__global__ __launch_bounds__(256) void fc_tc(const float* __restrict__ W,
    const float* __restrict__ bias, float* __restrict__ out){
  extern __shared__ float sm[];
  gemm_db(g_attn, W, bias, out, 1, blockIdx.y*256, blockIdx.x*128, sm, threadIdx.x);
}

// ---------------------------------------------------------------------------
// Single-pass fused attention + in-kernel w normalization.
// 256 threads, 8 warps x 16 m-rows (MF=1), m-tile 128 rows. (Champion config.)
// p = exp(s/8); unnormalized p -> w region during nt loop; PV A-frags from p
// regs via shuffles; tail normalizes the block's own 128-row stripe.
// K/V smem ping-pong double-buffered, one barrier per tile.
// smem 96KB, regs ~128 -> 2 CTA/SM.
// ---------------------------------------------------------------------------
__global__ __launch_bounds__(256, 2) void attn_tc(float* w_region, int use_out){
  extern __shared__ float smem[];
  float* Qs = smem;                       // 8192 floats; reused as invl[128] later
  float* w_base = use_out ? w_region : g_wfallback;

  const int z = blockIdx.y;
  const int half = z & 1, bh = z >> 1, b = bh >> 4, h = bh & 15;
  const float* Q  = g_qh + (size_t)z * 131072;
  const float* Kp = g_kh + (size_t)z * 131072;
  const float* Vt = g_vh + (size_t)z * 131072;   // [d][t]
  float* Wout = w_base + (size_t)half * 134217728 + (size_t)bh * 4194304;

  const int tid = threadIdx.x, lane = tid & 31, w = tid >> 5;
  const int bm = blockIdx.x * 128;
  const int wm = w * 16;
  const int c = lane & 3, c2 = c * 2, lr = lane >> 2;
  const unsigned src0 = (lane & 28) | (c >> 1);
  const unsigned src1 = src0 | 2;
  const bool codd = (c & 1);

  load_tile256<128>(Qs,        Q + (size_t)bm*64 + 0,  64, tid);
  load_tile256<128>(Qs + 4096, Q + (size_t)bm*64 + 32, 64, tid);

  // preload tile 0 into buffer 0
  {
    float* Kb = smem + 8192;
    float* Vb = smem + 8192 + 4096;
    load_tile256<64>(Kb,        Kp + 0,  64, tid);
    load_tile256<64>(Kb + 2048, Kp + 32, 64, tid);
    load_tile256<64>(Vb,        Vt + 0,  2048, tid);
    load_tile256<64>(Vb + 2048, Vt + 32, 2048, tid);
  }

  float lrow[2] = {0.f, 0.f};
  float oacc[8][4] = {};

  #pragma unroll 1
  for (int nt = 0; nt < 32; nt++){
    __syncthreads();
    float* Kb = smem + 8192 + (nt & 1)*8192;
    float* Vb = Kb + 4096;
    if (nt < 31){
      float* Kn = smem + 8192 + ((nt+1) & 1)*8192;
      float* Vn = Kn + 4096;
      load_tile256<64>(Kn,        Kp + (size_t)(nt+1)*4096 + 0,  64, tid);
      load_tile256<64>(Kn + 2048, Kp + (size_t)(nt+1)*4096 + 32, 64, tid);
      load_tile256<64>(Vn,        Vt + (nt+1)*64 + 0,  2048, tid);
      load_tile256<64>(Vn + 2048, Vt + (nt+1)*64 + 32, 2048, tid);
    }

    float sacc[1][8][4] = {};
    mma_core<1,8>(Qs,        Kb,        lane, wm, 0, sacc);
    mma_core<1,8>(Qs + 4096, Kb + 2048, lane, wm, 0, sacc);

    // p = exp(s/8), global w store (unnormalized), round p in place for PV
    #pragma unroll
    for (int rr = 0; rr < 2; rr++){
      const int r = wm + lr + rr*8;
      size_t gbase = (size_t)(bm + r) * 2048 + nt*64 + c2;
      float lsum = 0.f;
      #pragma unroll
      for (int nf = 0; nf < 8; nf++){
        float v0 = __expf(sacc[0][nf][rr*2]   * 0.125f);
        float v1 = __expf(sacc[0][nf][rr*2+1] * 0.125f);
        lsum += v0 + v1;
        *(float2*)(Wout + gbase + nf*8) = make_float2(v0, v1);
        sacc[0][nf][rr*2]   = tf32r(v0);
        sacc[0][nf][rr*2+1] = tf32r(v1);
      }
      lrow[rr] += lsum;
    }

    // PV: O += p @ V, A-fragments via shuffles from sacc
    #pragma unroll
    for (int ch = 0; ch < 2; ch++){
      const float* Vc = Vb + ch*2048;
      #pragma unroll
      for (int gg = 0; gg < 2; gg++){
        float A[2][4];
        #pragma unroll
        for (int hh = 0; hh < 2; hh++){
          const int g = ch*4 + gg*2 + hh;
          float s0 = __shfl_sync(0xffffffffu, sacc[0][g][0], src0);
          float s1 = __shfl_sync(0xffffffffu, sacc[0][g][1], src0);
          float s2 = __shfl_sync(0xffffffffu, sacc[0][g][2], src0);
          float s3 = __shfl_sync(0xffffffffu, sacc[0][g][3], src0);
          A[hh][0] = codd ? s1 : s0;
          A[hh][1] = codd ? s3 : s2;
          float t0 = __shfl_sync(0xffffffffu, sacc[0][g][0], src1);
          float t1 = __shfl_sync(0xffffffffu, sacc[0][g][1], src1);
          float t2 = __shfl_sync(0xffffffffu, sacc[0][g][2], src1);
          float t3 = __shfl_sync(0xffffffffu, sacc[0][g][3], src1);
          A[hh][2] = codd ? t1 : t0;
          A[hh][3] = codd ? t3 : t2;
        }
        #pragma unroll
        for (int nf = 0; nf < 8; nf++){
          const int n = nf*8 + lr;
          float4 bf = *(const float4*)(Vc + n*32 + ((gg ^ (n & 1)) << 4) + ((c ^ ((n >> 1) & 3)) << 2));
          mma8(oacc[nf], A[0][0], A[0][1], A[0][2], A[0][3], bf.x, bf.y);
          mma8(oacc[nf], A[1][0], A[1][1], A[1][2], A[1][3], bf.z, bf.w);
        }
      }
    }
  }

  // quad-reduce row sums, invert
  float invl[2];
  #pragma unroll
  for (int rr = 0; rr < 2; rr++){
    float s = lrow[rr];
    s += __shfl_xor_sync(0xffffffffu, s, 1);
    s += __shfl_xor_sync(0xffffffffu, s, 2);
    invl[rr] = 1.0f / s;
  }

  // O epilogue (scaled): g_attn[b][half*2048+m][h*64+d]
  #pragma unroll
  for (int rr = 0; rr < 2; rr++){
    int m = bm + wm + lr + rr*8;
    const float s = invl[rr];
    size_t obase = ((size_t)b*4096 + (size_t)half*2048 + m) * 1024 + h*64;
    #pragma unroll
    for (int nf = 0; nf < 8; nf++){
      int d = nf*8 + c2;
      float2 o;
      o.x = oacc[nf][rr*2+0] * s;
      o.y = oacc[nf][rr*2+1] * s;
      *(float2*)(g_attn + obase + d) = o;
    }
  }

  // ---- tail: normalize this block's own 128 w rows ----
  __syncthreads();                 // all in-loop w STGs done & visible CTA-wide
  if (c == 0){
    Qs[wm + lr]     = invl[0];
    Qs[wm + lr + 8] = invl[1];
  }
  __syncthreads();
  float4* wp = (float4*)(Wout + (size_t)bm * 2048);
  #pragma unroll 4
  for (int i = tid; i < 128*512; i += 256){
    const int row = i >> 9;
    const float s = Qs[row];
    float4 v = wp[i];
    v.x *= s; v.y *= s; v.z *= s; v.w *= s;
    wp[i] = v;
  }
}

// ---------------------------------------------------------------------------
extern "C" void kernel_launch(void* const* d_in, const int* in_sizes, int n_in,
                              void* d_out, int out_size)
{
  const float* q    = (const float*)d_in[0];
  const float* k    = (const float*)d_in[1];
  const float* v    = (const float*)d_in[2];
  const float* wq_w = (const float*)d_in[3];
  const float* wq_b = (const float*)d_in[4];
  const float* wk_w = (const float*)d_in[5];
  const float* wk_b = (const float*)d_in[6];
  const float* wv_w = (const float*)d_in[7];
  const float* wv_b = (const float*)d_in[8];
  const float* fc_w = (const float*)d_in[9];
  const float* fc_b = (const float*)d_in[10];
  float* out = (float*)d_out;

  const int w_in_out = (out_size >= 276824064) ? 1 : 0;
  float* w_region = out + 8388608;

  cudaFuncSetAttribute(attn_tc,  cudaFuncAttributeMaxDynamicSharedMemorySize, 98304);
  cudaFuncSetAttribute(proj3_tc, cudaFuncAttributeMaxDynamicSharedMemorySize, 98304);
  cudaFuncSetAttribute(fc_tc,    cudaFuncAttributeMaxDynamicSharedMemorySize, 98304);

  proj3_tc<<<dim3(8, 32, 3), 256, 98304>>>(q, k, v, wq_w, wq_b, wk_w, wk_b, wv_w, wv_b);
  attn_tc<<<dim3(16, 64), 256, 98304>>>(w_region, w_in_out);
  fc_tc<<<dim3(8, 32), 256, 98304>>>(fc_w, fc_b, out);
}